// round 12
// baseline (speedup 1.0000x reference)
#include <cuda_runtime.h>
#include <math.h>

#define BB 8
#define CC 64
#define NN 256
#define M1 20
#define M2 20
#define RR 40
#define MODES 800
#define LL 3
#define FCN 128

// ---------------- device scratch (channel-last h: [b][x][y][c]) ----------------
__device__ float g_h[BB * NN * NN * CC];
__device__ float g_t1p[BB * NN * M2 * CC];        // [b][x][s][c]
__device__ float g_spec[MODES * BB * CC];         // [m][b][c]
__device__ float g_spec2[BB * CC * MODES];        // [(b,o)][m]
__device__ float g_t2[BB * NN * M2 * CC];         // [b][x][s][o]
__device__ float g_Wm[LL * MODES * CC * CC];
__device__ float g_F1[RR * NN];
__device__ float g_F2[M2 * NN];
__device__ float g_G1[NN * RR];
__device__ float g_G2[NN * M2];

// ---------------- helpers ----------------
__device__ __forceinline__ unsigned f2tf(float f) {
    unsigned u; asm("cvt.rna.tf32.f32 %0,%1;" : "=r"(u) : "f"(f)); return u;
}
__device__ __forceinline__ void split_tf(float v, unsigned& hi, unsigned& lo) {
    unsigned h = f2tf(v);
    hi = h;
    lo = f2tf(v - __uint_as_float(h));
}
__device__ __forceinline__ void mma8(float& d0, float& d1, float& d2, float& d3,
                                     unsigned a0, unsigned a1, unsigned a2, unsigned a3,
                                     unsigned b0, unsigned b1) {
    asm("mma.sync.aligned.m16n8k8.row.col.f32.tf32.tf32.f32 "
        "{%0,%1,%2,%3},{%4,%5,%6,%7},{%8,%9},{%0,%1,%2,%3};"
        : "+f"(d0), "+f"(d1), "+f"(d2), "+f"(d3)
        : "r"(a0), "r"(a1), "r"(a2), "r"(a3), "r"(b0), "r"(b1));
}
#define MMA3(ACC, AH0,AH1,AH2,AH3, AL0,AL1,AL2,AL3, BH0,BH1, BL0,BL1)             \
    do {                                                                           \
        mma8(ACC[0],ACC[1],ACC[2],ACC[3], AH0,AH1,AH2,AH3, BL0,BL1);               \
        mma8(ACC[0],ACC[1],ACC[2],ACC[3], AL0,AL1,AL2,AL3, BH0,BH1);               \
        mma8(ACC[0],ACC[1],ACC[2],ACC[3], AH0,AH1,AH2,AH3, BH0,BH1);               \
    } while (0)

__device__ __forceinline__ float ftanh(float x) {
    float e = __expf(2.f * x);
    return 1.f - __fdividef(2.f, e + 1.f);
}

// ---------------- DCT basis tables ----------------
__global__ void k_init() {
    int x = blockIdx.x, t = threadIdx.x;
    if (t < RR) {
        int k = (t < M1) ? t : (216 + t);
        int m = (k * x) % 510;
        float cv = (float)cospi((double)m / 255.0);
        float cx = (x == 0 || x == 255) ? 1.f : 2.f;
        g_F1[t * NN + x] = cx * cv;
        float ck = (k == 0 || k == 255) ? 1.f : 2.f;
        g_G1[x * RR + t] = ck * cv;
    }
    if (t < M2) {
        int m = (t * x) % 510;
        float cv = (float)cospi((double)m / 255.0);
        float cy = (x == 0 || x == 255) ? 1.f : 2.f;
        g_F2[t * NN + x] = cy * cv;
        float cs = (t == 0) ? 1.f : 2.f;
        g_G2[x * M2 + t] = cs * cv;
    }
}

// ---------------- spectral weight transpose ----------------
__global__ void k_wtrans(const float* __restrict__ w1, const float* __restrict__ w2) {
    __shared__ float tile[32][33];
    int l = blockIdx.z >> 1, half = blockIdx.z & 1;
    const float* src = (half ? w2 : w1) + (size_t)l * CC * CC * (M1 * M2);
    float* dst = g_Wm + ((size_t)l * MODES + half * 400) * (CC * CC);
    int col = blockIdx.x * 32 + threadIdx.x;
    int row = blockIdx.y * 32 + threadIdx.y;
    if (col < 400) tile[threadIdx.y][threadIdx.x] = src[(size_t)row * 400 + col];
    __syncthreads();
    int drow = blockIdx.x * 32 + threadIdx.y;
    int dcol = blockIdx.y * 32 + threadIdx.x;
    if (drow < 400) dst[(size_t)drow * 4096 + dcol] = tile[threadIdx.x][threadIdx.y];
}

// ---------------- fc0 (channel-last output) ----------------
__global__ __launch_bounds__(256) void k_fc0(const float* __restrict__ x,
                                             const float* __restrict__ w,
                                             const float* __restrict__ bias) {
    __shared__ float sw[3][CC];
    __shared__ float sb[CC];
    __shared__ float sx[NN * 3];
    int xi = blockIdx.x, b = blockIdx.y, tid = threadIdx.x;
    if (tid < CC) { sw[0][tid] = w[tid]; sw[1][tid] = w[CC + tid]; sw[2][tid] = w[2 * CC + tid]; sb[tid] = bias[tid]; }
    size_t xbase = (((size_t)b * NN + xi) * NN) * 3;
    for (int i = tid; i < NN * 3; i += 256) sx[i] = x[xbase + i];
    __syncthreads();
    float* hp = g_h + (((size_t)b * NN + xi) * NN) * CC;
    for (int idx = tid; idx < NN * CC; idx += 256) {
        int y = idx >> 6, c = idx & 63;
        hp[idx] = sb[c] + sx[y * 3] * sw[0][c] + sx[y * 3 + 1] * sw[1][c] + sx[y * 3 + 2] * sw[2][c];
    }
}

// ---------------- forward y-DCT: t1p[b][x][s][c] = sum_y F2[s][y] * h[b][x][y][c] -----------
// per (b,x): M=32 (20 used), K=256 (y), N=64 (c). 8 warps: kh = wid>>2 K-split.
__global__ __launch_bounds__(256) void k_s1cl() {
    extern __shared__ float smf[];
    float* sF2 = smf;                 // [32][260]
    float* sB  = smf + 32 * 260;      // [256][72]
    int x = blockIdx.x, b = blockIdx.y, tid = threadIdx.x;
    int wid = tid >> 5, lane = tid & 31, gid = lane >> 2, tig = lane & 3;
    int kh = wid >> 2, mt = wid & 1, ng = (wid >> 1) & 1;
    int mtb = mt * 16;

    for (int idx = tid; idx < 32 * NN; idx += 256) {
        int s = idx >> 8, y = idx & 255;
        sF2[s * 260 + y] = (s < 20) ? g_F2[s * NN + y] : 0.f;
    }
    const float4* hp = (const float4*)(g_h + (((size_t)b * NN + x) * NN) * CC);
    for (int idx = tid; idx < NN * 16; idx += 256) {
        int y = idx >> 4, c4 = idx & 15;
        float4 v = hp[y * 16 + c4];
        float* d = &sB[y * 72 + c4 * 4];
        d[0] = v.x; d[1] = v.y; d[2] = v.z; d[3] = v.w;
    }
    __syncthreads();

    float acc[4][4];
#pragma unroll
    for (int i = 0; i < 4; i++) { acc[i][0] = acc[i][1] = acc[i][2] = acc[i][3] = 0.f; }

#pragma unroll 2
    for (int ks = 0; ks < 16; ks++) {
        int k0 = kh * 128 + ks * 8;
        unsigned ah0, al0, ah1, al1, ah2, al2, ah3, al3;
        split_tf(sF2[(mtb + gid) * 260 + k0 + tig], ah0, al0);
        split_tf(sF2[(mtb + gid + 8) * 260 + k0 + tig], ah1, al1);
        split_tf(sF2[(mtb + gid) * 260 + k0 + tig + 4], ah2, al2);
        split_tf(sF2[(mtb + gid + 8) * 260 + k0 + tig + 4], ah3, al3);
#pragma unroll
        for (int nt = 0; nt < 4; nt++) {
            int n = (ng * 4 + nt) * 8 + gid;
            unsigned bh0, bl0, bh1, bl1;
            split_tf(sB[(k0 + tig) * 72 + n], bh0, bl0);
            split_tf(sB[(k0 + tig + 4) * 72 + n], bh1, bl1);
            MMA3(acc[nt], ah0,ah1,ah2,ah3, al0,al1,al2,al3, bh0,bh1, bl0,bl1);
        }
    }

    __syncthreads();
    float* red = smf;                  // reuse sF2 region: [2][32][64]
#pragma unroll
    for (int nt = 0; nt < 4; nt++) {
        int n0 = (ng * 4 + nt) * 8 + tig * 2;
        *(float2*)&red[kh * 2048 + (mtb + gid) * 64 + n0] = make_float2(acc[nt][0], acc[nt][1]);
        *(float2*)&red[kh * 2048 + (mtb + gid + 8) * 64 + n0] = make_float2(acc[nt][2], acc[nt][3]);
    }
    __syncthreads();
    float* tp = g_t1p + ((size_t)b * NN + x) * (M2 * CC);
    for (int idx = tid; idx < 32 * 64; idx += 256) {
        int m = idx >> 6;
        if (m < M2) tp[idx] = red[idx] + red[2048 + idx];
    }
}

// ---------------- forward x-DCT (streaming MMA): spec[m][b][c] = sum_x F1[r][x]*t1p[b][x][n] -
// per (b, n-chunk of 128): M=48 (40 used), K=256 (x), N=128 of (s,c)=1280.
__global__ __launch_bounds__(256) void k_s2cl() {
    extern __shared__ float smf[];
    float* sF1 = smf;                 // [48][260]
    float* sB  = smf + 48 * 260;      // [32][136]
    int nc = blockIdx.x, b = blockIdx.y, tid = threadIdx.x;
    int wid = tid >> 5, lane = tid & 31, gid = lane >> 2, tig = lane & 3;
    int n0 = nc * 128;

    for (int idx = tid; idx < 48 * NN; idx += 256) {
        int r = idx >> 8, xx = idx & 255;
        sF1[r * 260 + xx] = (r < RR) ? g_F1[r * NN + xx] : 0.f;
    }

    float acc[3][2][4];
#pragma unroll
    for (int m = 0; m < 3; m++)
#pragma unroll
        for (int j = 0; j < 2; j++) { acc[m][j][0] = acc[m][j][1] = acc[m][j][2] = acc[m][j][3] = 0.f; }

    const float* tb = g_t1p + (size_t)b * NN * (M2 * CC);
    for (int ch = 0; ch < 8; ch++) {
        __syncthreads();
        for (int idx = tid; idx < 32 * 128; idx += 256) {
            int row = idx >> 7, cn = idx & 127;
            sB[row * 136 + cn] = tb[(size_t)(ch * 32 + row) * (M2 * CC) + n0 + cn];
        }
        __syncthreads();
#pragma unroll
        for (int ks = 0; ks < 4; ks++) {
            int kk = ch * 32 + ks * 8;      // global k (for A)
            int kl = ks * 8;                // local k (for B)
            unsigned ah[3][4], al[3][4];
#pragma unroll
            for (int m = 0; m < 3; m++) {
                split_tf(sF1[(m * 16 + gid) * 260 + kk + tig], ah[m][0], al[m][0]);
                split_tf(sF1[(m * 16 + gid + 8) * 260 + kk + tig], ah[m][1], al[m][1]);
                split_tf(sF1[(m * 16 + gid) * 260 + kk + tig + 4], ah[m][2], al[m][2]);
                split_tf(sF1[(m * 16 + gid + 8) * 260 + kk + tig + 4], ah[m][3], al[m][3]);
            }
#pragma unroll
            for (int j = 0; j < 2; j++) {
                int n = (wid * 2 + j) * 8 + gid;
                unsigned bh0, bl0, bh1, bl1;
                split_tf(sB[(kl + tig) * 136 + n], bh0, bl0);
                split_tf(sB[(kl + tig + 4) * 136 + n], bh1, bl1);
#pragma unroll
                for (int m = 0; m < 3; m++)
                    MMA3(acc[m][j], ah[m][0],ah[m][1],ah[m][2],ah[m][3],
                                    al[m][0],al[m][1],al[m][2],al[m][3], bh0,bh1, bl0,bl1);
            }
        }
    }

#pragma unroll
    for (int m = 0; m < 3; m++) {
#pragma unroll
        for (int j = 0; j < 2; j++) {
            int n = n0 + (wid * 2 + j) * 8 + tig * 2;
            int s = n >> 6, c = n & 63;
            int r0 = m * 16 + gid, r1 = r0 + 8;
            if (r0 < RR)
                *(float2*)&g_spec[(size_t)(r0 * M2 + s) * (BB * CC) + b * CC + c] =
                    make_float2(acc[m][j][0], acc[m][j][1]);
            if (r1 < RR)
                *(float2*)&g_spec[(size_t)(r1 * M2 + s) * (BB * CC) + b * CC + c] =
                    make_float2(acc[m][j][2], acc[m][j][3]);
        }
    }
}

// ---------------- per-mode channel mix (exact fp32) ----------------
__global__ __launch_bounds__(256) void k_mix(int l) {
    __shared__ float sW[CC * CC];
    __shared__ float sS[BB * CC];
    int m = blockIdx.x, t = threadIdx.x;
    const float* Wp = g_Wm + ((size_t)l * MODES + m) * (CC * CC);
    for (int i = t; i < CC * CC; i += 256) sW[i] = Wp[i];
    for (int i = t; i < BB * CC; i += 256) sS[i] = g_spec[(size_t)m * (BB * CC) + i];
    __syncthreads();
#pragma unroll
    for (int k = 0; k < 2; k++) {
        int idx = t + k * 256;
        int b = idx >> 6, o = idx & 63;
        float acc = 0.f;
#pragma unroll
        for (int i = 0; i < CC; i++) acc += sS[b * CC + i] * sW[i * CC + o];
        g_spec2[(size_t)(b * CC + o) * MODES + m] = acc;
    }
}

// ---------------- inverse x-DCT (exact fp32): t2[b][x][s][o] ----------------
__global__ __launch_bounds__(256) void k_istage1() {
    __shared__ float sS[MODES];
    int bo = blockIdx.x, x = threadIdx.x;
    int b = bo >> 6, o = bo & 63;
    for (int i = x; i < MODES; i += 256) sS[i] = g_spec2[(size_t)bo * MODES + i];
    __syncthreads();
    float g1r[RR];
    const float4* gp = (const float4*)(g_G1 + x * RR);
#pragma unroll
    for (int j = 0; j < RR / 4; j++) {
        float4 v = gp[j];
        g1r[4 * j] = v.x; g1r[4 * j + 1] = v.y; g1r[4 * j + 2] = v.z; g1r[4 * j + 3] = v.w;
    }
    float acc[M2];
#pragma unroll
    for (int s = 0; s < M2; s++) acc[s] = 0.f;
#pragma unroll 4
    for (int r = 0; r < RR; r++) {
        float g = g1r[r];
#pragma unroll
        for (int s = 0; s < M2; s++) acc[s] += g * sS[r * M2 + s];
    }
    float* tp = g_t2 + (((size_t)b * NN + x) * M2) * CC + o;
#pragma unroll
    for (int s = 0; s < M2; s++) tp[s * CC] = acc[s];
}

// ---------------- fused layer update (channel-last streaming MMA, in place) -------------
// per (yh, x, b): out[pix][o] = H[pix][i]*CWT[i][o] + G2[y][s]*t2[s][o] + bias, [tanh]
// M=128 pixels, N=64, K=88 (64 conv + 20 idct + 4 pad)
__global__ __launch_bounds__(512) void k_ilayer(const float* __restrict__ conv_w,
                                                const float* __restrict__ conv_b,
                                                int l, int do_tanh) {
    extern __shared__ float smf[];
    unsigned* sBh = (unsigned*)smf;           // [88][72]
    unsigned* sBl = sBh + 88 * 72;            // [88][72]
    float* sA = (float*)(sBl + 88 * 72);      // [128][92]
    int yh = blockIdx.x, x = blockIdx.y, b = blockIdx.z, tid = threadIdx.x;
    int wid = tid >> 5, lane = tid & 31, gid = lane >> 2, tig = lane & 3;
    int mt = wid & 7, nh = wid >> 3;
    int mtb = mt * 16;

    // B: conv weights transposed (rows 0..63) + t2 slab (rows 64..83) + zero pad
    const float* cw = conv_w + (size_t)l * CC * CC;
    for (int idx = tid; idx < CC * CC; idx += 512) {
        int o = idx >> 6, i = idx & 63;
        unsigned h, lo; split_tf(cw[idx], h, lo);
        sBh[i * 72 + o] = h; sBl[i * 72 + o] = lo;
    }
    const float* t2p = g_t2 + (((size_t)b * NN + x) * M2) * CC;
    for (int idx = tid; idx < M2 * CC; idx += 512) {
        unsigned h, lo; split_tf(t2p[idx], h, lo);
        int s = idx >> 6, o = idx & 63;
        sBh[(64 + s) * 72 + o] = h; sBl[(64 + s) * 72 + o] = lo;
    }
    for (int idx = tid; idx < 4 * CC; idx += 512) {
        int kk = idx >> 6, o = idx & 63;
        sBh[(84 + kk) * 72 + o] = 0u; sBl[(84 + kk) * 72 + o] = 0u;
    }
    // A: h pixels (cols 0..63) + G2 rows (cols 64..87)
    float* hbase = g_h + (((size_t)b * NN + x) * NN + yh * 128) * CC;
    const float4* hp4 = (const float4*)hbase;
    for (int idx = tid; idx < 128 * 16; idx += 512) {
        int row = idx >> 4, c4 = idx & 15;
        float4 v = hp4[row * 16 + c4];
        float* d = &sA[row * 92 + c4 * 4];
        d[0] = v.x; d[1] = v.y; d[2] = v.z; d[3] = v.w;
    }
    for (int idx = tid; idx < 128 * 24; idx += 512) {
        int row = idx / 24, s = idx % 24;
        sA[row * 92 + 64 + s] = (s < 20) ? g_G2[(yh * 128 + row) * M2 + s] : 0.f;
    }
    __syncthreads();

    float acc[4][4];
#pragma unroll
    for (int nt = 0; nt < 4; nt++) {
        int n0 = nh * 32 + nt * 8 + tig * 2;
        float c0 = __ldg(&conv_b[l * CC + n0]);
        float c1 = __ldg(&conv_b[l * CC + n0 + 1]);
        acc[nt][0] = c0; acc[nt][1] = c1; acc[nt][2] = c0; acc[nt][3] = c1;
    }

#pragma unroll
    for (int ks = 0; ks < 11; ks++) {
        int k0 = ks * 8;
        unsigned ah0, al0, ah1, al1, ah2, al2, ah3, al3;
        split_tf(sA[(mtb + gid) * 92 + k0 + tig], ah0, al0);
        split_tf(sA[(mtb + gid + 8) * 92 + k0 + tig], ah1, al1);
        split_tf(sA[(mtb + gid) * 92 + k0 + tig + 4], ah2, al2);
        split_tf(sA[(mtb + gid + 8) * 92 + k0 + tig + 4], ah3, al3);
#pragma unroll
        for (int nt = 0; nt < 4; nt++) {
            int n = nh * 32 + nt * 8 + gid;
            unsigned bh0 = sBh[(k0 + tig) * 72 + n];
            unsigned bh1 = sBh[(k0 + tig + 4) * 72 + n];
            unsigned bl0 = sBl[(k0 + tig) * 72 + n];
            unsigned bl1 = sBl[(k0 + tig + 4) * 72 + n];
            MMA3(acc[nt], ah0,ah1,ah2,ah3, al0,al1,al2,al3, bh0,bh1, bl0,bl1);
        }
    }

    __syncthreads();   // all reads of sA(h) complete before in-place write
#pragma unroll
    for (int nt = 0; nt < 4; nt++) {
        int n0 = nh * 32 + nt * 8 + tig * 2;
        int p0 = mtb + gid, p1 = p0 + 8;
        float d0 = acc[nt][0], d1 = acc[nt][1], d2 = acc[nt][2], d3 = acc[nt][3];
        if (do_tanh) { d0 = ftanh(d0); d1 = ftanh(d1); d2 = ftanh(d2); d3 = ftanh(d3); }
        *(float2*)&hbase[(size_t)p0 * CC + n0] = make_float2(d0, d1);
        *(float2*)&hbase[(size_t)p1 * CC + n0] = make_float2(d2, d3);
    }
}

// ---------------- fc1 (tanh) + fc2 fused (channel-last streaming MMA) ----------------
__global__ __launch_bounds__(512) void k_fc12(const float* __restrict__ w1,
                                              const float* __restrict__ b1,
                                              const float* __restrict__ w2,
                                              const float* __restrict__ b2,
                                              float* __restrict__ out) {
    extern __shared__ float smf[];
    unsigned* sBh = (unsigned*)smf;           // [64][136]
    unsigned* sBl = sBh + 64 * 136;
    float* sA   = (float*)(sBl + 64 * 136);   // [128][76]
    float* sred = sA + 128 * 76;              // [128]
    float* sb1  = sred + 128;                 // [128]
    float* sw2  = sb1 + 128;                  // [128]
    int yh = blockIdx.x, x = blockIdx.y, b = blockIdx.z, tid = threadIdx.x;
    int wid = tid >> 5, lane = tid & 31, gid = lane >> 2, tig = lane & 3;
    int mt = wid & 7, nh = wid >> 3;
    int mtb = mt * 16;

    for (int idx = tid; idx < CC * FCN; idx += 512) {
        unsigned h, lo; split_tf(w1[idx], h, lo);
        int c = idx >> 7, f = idx & 127;
        sBh[c * 136 + f] = h; sBl[c * 136 + f] = lo;
    }
    const float* hbase = g_h + (((size_t)b * NN + x) * NN + yh * 128) * CC;
    const float4* hp4 = (const float4*)hbase;
    for (int idx = tid; idx < 128 * 16; idx += 512) {
        int row = idx >> 4, c4 = idx & 15;
        float4 v = hp4[row * 16 + c4];
        float* d = &sA[row * 76 + c4 * 4];
        d[0] = v.x; d[1] = v.y; d[2] = v.z; d[3] = v.w;
    }
    if (tid < 128) { sred[tid] = 0.f; sb1[tid] = b1[tid]; sw2[tid] = w2[tid]; }
    __syncthreads();

    float acc[8][4];
#pragma unroll
    for (int nt = 0; nt < 8; nt++) {
        int f0 = nh * 64 + nt * 8 + tig * 2;
        float c0 = sb1[f0], c1 = sb1[f0 + 1];
        acc[nt][0] = c0; acc[nt][1] = c1; acc[nt][2] = c0; acc[nt][3] = c1;
    }

#pragma unroll
    for (int ks = 0; ks < 8; ks++) {
        int k0 = ks * 8;
        unsigned ah0, al0, ah1, al1, ah2, al2, ah3, al3;
        split_tf(sA[(mtb + gid) * 76 + k0 + tig], ah0, al0);
        split_tf(sA[(mtb + gid + 8) * 76 + k0 + tig], ah1, al1);
        split_tf(sA[(mtb + gid) * 76 + k0 + tig + 4], ah2, al2);
        split_tf(sA[(mtb + gid + 8) * 76 + k0 + tig + 4], ah3, al3);
#pragma unroll
        for (int nt = 0; nt < 8; nt++) {
            int n = nh * 64 + nt * 8 + gid;
            unsigned bh0 = sBh[(k0 + tig) * 136 + n];
            unsigned bh1 = sBh[(k0 + tig + 4) * 136 + n];
            unsigned bl0 = sBl[(k0 + tig) * 136 + n];
            unsigned bl1 = sBl[(k0 + tig + 4) * 136 + n];
            MMA3(acc[nt], ah0,ah1,ah2,ah3, al0,al1,al2,al3, bh0,bh1, bl0,bl1);
        }
    }

    float p0 = 0.f, p1 = 0.f;
#pragma unroll
    for (int nt = 0; nt < 8; nt++) {
        int f0 = nh * 64 + nt * 8 + tig * 2;
        float wa = sw2[f0], wb = sw2[f0 + 1];
        p0 += ftanh(acc[nt][0]) * wa + ftanh(acc[nt][1]) * wb;
        p1 += ftanh(acc[nt][2]) * wa + ftanh(acc[nt][3]) * wb;
    }
    p0 += __shfl_xor_sync(0xffffffffu, p0, 1);
    p0 += __shfl_xor_sync(0xffffffffu, p0, 2);
    p1 += __shfl_xor_sync(0xffffffffu, p1, 1);
    p1 += __shfl_xor_sync(0xffffffffu, p1, 2);
    if (tig == 0) {
        atomicAdd(&sred[mtb + gid], p0);
        atomicAdd(&sred[mtb + gid + 8], p1);
    }
    __syncthreads();
    if (tid < 128)
        out[(((size_t)b * NN + x) * NN) + yh * 128 + tid] = sred[tid] + __ldg(&b2[0]);
}

// ---------------- launch ----------------
extern "C" void kernel_launch(void* const* d_in, const int* in_sizes, int n_in,
                              void* d_out, int out_size) {
    const float* x      = (const float*)d_in[0];
    const float* fc0_w  = (const float*)d_in[1];
    const float* fc0_b  = (const float*)d_in[2];
    const float* sp_w1  = (const float*)d_in[3];
    const float* sp_w2  = (const float*)d_in[4];
    const float* conv_w = (const float*)d_in[5];
    const float* conv_b = (const float*)d_in[6];
    const float* fc1_w  = (const float*)d_in[7];
    const float* fc1_b  = (const float*)d_in[8];
    const float* fc2_w  = (const float*)d_in[9];
    const float* fc2_b  = (const float*)d_in[10];
    float* out = (float*)d_out;

    const int SM_S1  = (32 * 260 + 256 * 72) * 4;                      // 107008
    const int SM_S2  = (48 * 260 + 32 * 136) * 4;                      // 67328
    const int SM_IL  = (2 * 88 * 72 + 128 * 92) * 4;                   // 97792
    const int SM_FC  = (2 * 64 * 136 + 128 * 76 + 128 * 3) * 4;        // 110080

    cudaFuncSetAttribute(k_s1cl, cudaFuncAttributeMaxDynamicSharedMemorySize, SM_S1);
    cudaFuncSetAttribute(k_s2cl, cudaFuncAttributeMaxDynamicSharedMemorySize, SM_S2);
    cudaFuncSetAttribute(k_ilayer, cudaFuncAttributeMaxDynamicSharedMemorySize, SM_IL);
    cudaFuncSetAttribute(k_fc12, cudaFuncAttributeMaxDynamicSharedMemorySize, SM_FC);

    k_init<<<NN, 256>>>();
    k_wtrans<<<dim3(13, 128, LL * 2), dim3(32, 32)>>>(sp_w1, sp_w2);
    k_fc0<<<dim3(NN, BB), 256>>>(x, fc0_w, fc0_b);

    for (int l = 0; l < LL; l++) {
        k_s1cl<<<dim3(NN, BB), 256, SM_S1>>>();
        k_s2cl<<<dim3(10, BB), 256, SM_S2>>>();
        k_mix<<<MODES, 256>>>(l);
        k_istage1<<<BB * CC, 256>>>();
        k_ilayer<<<dim3(2, NN, BB), 512, SM_IL>>>(conv_w, conv_b, l, (l != LL - 1) ? 1 : 0);
    }

    k_fc12<<<dim3(2, NN, BB), 512, SM_FC>>>(fc1_w, fc1_b, fc2_w, fc2_b, out);
}

// round 13
// speedup vs baseline: 1.1356x; 1.1356x over previous
#include <cuda_runtime.h>
#include <math.h>

#define BB 8
#define CC 64
#define NN 256
#define M1 20
#define M2 20
#define RR 40
#define MODES 800
#define LL 3
#define FCN 128
#define BP 264          // B-matrix smem row pitch (floats)
#define AP 68           // A-matrix smem row pitch

// ---------------- device scratch ----------------
__device__ float g_h[BB * CC * NN * NN];
__device__ float g_t1p[BB * CC * NN * M2];         // y-first DCT temp [row=(bc,x)][s]
__device__ float g_spec[MODES * BB * CC];
__device__ float g_spec2[BB * CC * MODES];
__device__ float g_t2[BB * CC * NN * M2];
__device__ float g_Wm[LL * MODES * CC * CC];
__device__ float g_F1[RR * NN];
__device__ float g_F2[M2 * NN];
__device__ float g_G1[NN * RR];
__device__ float g_G2[NN * M2];

// ---------------- helpers ----------------
__device__ __forceinline__ unsigned f2tf(float f) {
    unsigned u; asm("cvt.rna.tf32.f32 %0,%1;" : "=r"(u) : "f"(f)); return u;
}
__device__ __forceinline__ void split_tf(float v, unsigned& hi, unsigned& lo) {
    unsigned h = f2tf(v);
    hi = h;
    lo = f2tf(v - __uint_as_float(h));
}
__device__ __forceinline__ void mma8(float& d0, float& d1, float& d2, float& d3,
                                     unsigned a0, unsigned a1, unsigned a2, unsigned a3,
                                     unsigned b0, unsigned b1) {
    asm("mma.sync.aligned.m16n8k8.row.col.f32.tf32.tf32.f32 "
        "{%0,%1,%2,%3},{%4,%5,%6,%7},{%8,%9},{%0,%1,%2,%3};"
        : "+f"(d0), "+f"(d1), "+f"(d2), "+f"(d3)
        : "r"(a0), "r"(a1), "r"(a2), "r"(a3), "r"(b0), "r"(b1));
}
#define MMA3(ACC, AH0,AH1,AH2,AH3, AL0,AL1,AL2,AL3, BH0,BH1, BL0,BL1)             \
    do {                                                                           \
        mma8(ACC[0],ACC[1],ACC[2],ACC[3], AH0,AH1,AH2,AH3, BL0,BL1);               \
        mma8(ACC[0],ACC[1],ACC[2],ACC[3], AL0,AL1,AL2,AL3, BH0,BH1);               \
        mma8(ACC[0],ACC[1],ACC[2],ACC[3], AH0,AH1,AH2,AH3, BH0,BH1);               \
    } while (0)
// split-accumulator form: compensation terms into ACG (shorter chains)
#define MMA3S(ACC, ACG, AH0,AH1,AH2,AH3, AL0,AL1,AL2,AL3, BH0,BH1, BL0,BL1)       \
    do {                                                                           \
        mma8(ACG[0],ACG[1],ACG[2],ACG[3], AH0,AH1,AH2,AH3, BL0,BL1);               \
        mma8(ACG[0],ACG[1],ACG[2],ACG[3], AL0,AL1,AL2,AL3, BH0,BH1);               \
        mma8(ACC[0],ACC[1],ACC[2],ACC[3], AH0,AH1,AH2,AH3, BH0,BH1);               \
    } while (0)

__device__ __forceinline__ float ftanh(float x) {
    float e = __expf(2.f * x);
    return 1.f - __fdividef(2.f, e + 1.f);
}

// ---------------- DCT basis tables ----------------
__global__ void k_init() {
    int x = blockIdx.x, t = threadIdx.x;
    if (t < RR) {
        int k = (t < M1) ? t : (216 + t);
        int m = (k * x) % 510;
        float cv = (float)cospi((double)m / 255.0);
        float cx = (x == 0 || x == 255) ? 1.f : 2.f;
        g_F1[t * NN + x] = cx * cv;
        float ck = (k == 0 || k == 255) ? 1.f : 2.f;
        g_G1[x * RR + t] = ck * cv;
    }
    if (t < M2) {
        int m = (t * x) % 510;
        float cv = (float)cospi((double)m / 255.0);
        float cy = (x == 0 || x == 255) ? 1.f : 2.f;
        g_F2[t * NN + x] = cy * cv;
        float cs = (t == 0) ? 1.f : 2.f;
        g_G2[x * M2 + t] = cs * cv;
    }
}

// ---------------- spectral weight transpose ----------------
__global__ void k_wtrans(const float* __restrict__ w1, const float* __restrict__ w2) {
    __shared__ float tile[32][33];
    int l = blockIdx.z >> 1, half = blockIdx.z & 1;
    const float* src = (half ? w2 : w1) + (size_t)l * CC * CC * (M1 * M2);
    float* dst = g_Wm + ((size_t)l * MODES + half * 400) * (CC * CC);
    int col = blockIdx.x * 32 + threadIdx.x;
    int row = blockIdx.y * 32 + threadIdx.y;
    if (col < 400) tile[threadIdx.y][threadIdx.x] = src[(size_t)row * 400 + col];
    __syncthreads();
    int drow = blockIdx.x * 32 + threadIdx.y;
    int dcol = blockIdx.y * 32 + threadIdx.x;
    if (drow < 400) dst[(size_t)drow * 4096 + dcol] = tile[threadIdx.x][threadIdx.y];
}

// ---------------- fc0 ----------------
__global__ void k_fc0(const float* __restrict__ x, const float* __restrict__ w,
                      const float* __restrict__ bias) {
    __shared__ float sw[3][CC];
    __shared__ float sb[CC];
    int xi = blockIdx.x, b = blockIdx.y, y = threadIdx.x;
    if (y < CC) { sw[0][y] = w[y]; sw[1][y] = w[CC + y]; sw[2][y] = w[2 * CC + y]; sb[y] = bias[y]; }
    __syncthreads();
    const float* xp = x + (((size_t)b * NN + xi) * NN + y) * 3;
    float d0 = xp[0], d1 = xp[1], d2 = xp[2];
    float* hp = g_h + ((size_t)(b * CC) * NN + xi) * NN + y;
#pragma unroll
    for (int c = 0; c < CC; c++)
        hp[(size_t)c * (NN * NN)] = sb[c] + d0 * sw[0][c] + d1 * sw[1][c] + d2 * sw[2][c];
}

// ---------------- forward DCT stage 1' (y-first, streaming 3xTF32, split accumulators) ----
__global__ __launch_bounds__(256) void k_s1p() {
    extern __shared__ unsigned smu[];
    unsigned* sBh = smu;               // [256][24]
    unsigned* sBl = smu + 256 * 24;
    int tid = threadIdx.x;
    int wid = tid >> 5, lane = tid & 31, gid = lane >> 2, tig = lane & 3;

    for (int idx = tid; idx < 256 * 24; idx += 256) {
        int y = idx / 24, s = idx % 24;
        float v = (s < 20) ? g_F2[s * NN + y] : 0.f;
        split_tf(v, sBh[idx], sBl[idx]);
    }
    __syncthreads();

    size_t row0 = (size_t)blockIdx.x * 128 + wid * 16;
    const float* A0 = g_h + (row0 + gid) * NN;
    const float* A1 = g_h + (row0 + gid + 8) * NN;

    float acc[3][4], acg[3][4];
#pragma unroll
    for (int i = 0; i < 3; i++) {
        acc[i][0] = acc[i][1] = acc[i][2] = acc[i][3] = 0.f;
        acg[i][0] = acg[i][1] = acg[i][2] = acg[i][3] = 0.f;
    }

#pragma unroll 4
    for (int k0 = 0; k0 < 256; k0 += 8) {
        float av0 = __ldg(&A0[k0 + tig]);
        float av1 = __ldg(&A1[k0 + tig]);
        float av2 = __ldg(&A0[k0 + tig + 4]);
        float av3 = __ldg(&A1[k0 + tig + 4]);
        unsigned ah0, al0, ah1, al1, ah2, al2, ah3, al3;
        split_tf(av0, ah0, al0); split_tf(av1, ah1, al1);
        split_tf(av2, ah2, al2); split_tf(av3, ah3, al3);
#pragma unroll
        for (int nt = 0; nt < 3; nt++) {
            int n = nt * 8 + gid;
            unsigned bh0 = sBh[(k0 + tig) * 24 + n];
            unsigned bh1 = sBh[(k0 + tig + 4) * 24 + n];
            unsigned bl0 = sBl[(k0 + tig) * 24 + n];
            unsigned bl1 = sBl[(k0 + tig + 4) * 24 + n];
            MMA3S(acc[nt], acg[nt], ah0,ah1,ah2,ah3, al0,al1,al2,al3, bh0,bh1, bl0,bl1);
        }
    }

    float* t0 = g_t1p + (row0 + gid) * M2;
    float* t1 = g_t1p + (row0 + gid + 8) * M2;
#pragma unroll
    for (int nt = 0; nt < 3; nt++) {
        int c0 = nt * 8 + tig * 2;
        if (c0 < 20) {
            *(float2*)&t0[c0] = make_float2(acc[nt][0] + acg[nt][0], acc[nt][1] + acg[nt][1]);
            *(float2*)&t1[c0] = make_float2(acc[nt][2] + acg[nt][2], acc[nt][3] + acg[nt][3]);
        }
    }
}

// ---------------- forward DCT stage 2' (x contraction, exact fp32) ----------------
__global__ __launch_bounds__(256) void k_s2p() {
    __shared__ float sS[NN * M2];      // [x][s]
    int bc = blockIdx.x, t = threadIdx.x;
    const float4* tp = (const float4*)(g_t1p + (size_t)bc * NN * M2);
    for (int i = t; i < NN * 5; i += 256) ((float4*)sS)[i] = tp[i];
    __syncthreads();
    if (t < 200) {
        int a = t / 5, q = t % 5;
        float4 acc = make_float4(0.f, 0.f, 0.f, 0.f);
        const float* f1 = g_F1 + a * NN;
#pragma unroll 4
        for (int x = 0; x < NN; x++) {
            float f = __ldg(&f1[x]);
            float4 v = *(const float4*)&sS[x * M2 + 4 * q];
            acc.x += f * v.x; acc.y += f * v.y; acc.z += f * v.z; acc.w += f * v.w;
        }
        int m0 = a * M2 + 4 * q;
        g_spec[(size_t)(m0 + 0) * (BB * CC) + bc] = acc.x;
        g_spec[(size_t)(m0 + 1) * (BB * CC) + bc] = acc.y;
        g_spec[(size_t)(m0 + 2) * (BB * CC) + bc] = acc.z;
        g_spec[(size_t)(m0 + 3) * (BB * CC) + bc] = acc.w;
    }
}

// ---------------- per-mode channel mix (exact fp32) ----------------
__global__ __launch_bounds__(256) void k_mix(int l) {
    __shared__ float sW[CC * CC];
    __shared__ float sS[BB * CC];
    int m = blockIdx.x, t = threadIdx.x;
    const float* Wp = g_Wm + ((size_t)l * MODES + m) * (CC * CC);
    for (int i = t; i < CC * CC; i += 256) sW[i] = Wp[i];
    for (int i = t; i < BB * CC; i += 256) sS[i] = g_spec[(size_t)m * (BB * CC) + i];
    __syncthreads();
#pragma unroll
    for (int k = 0; k < 2; k++) {
        int idx = t + k * 256;
        int b = idx >> 6, o = idx & 63;
        float acc = 0.f;
#pragma unroll
        for (int i = 0; i < CC; i++) acc += sS[b * CC + i] * sW[i * CC + o];
        g_spec2[(size_t)(b * CC + o) * MODES + m] = acc;
    }
}

// ---------------- inverse stage 1 (exact fp32) ----------------
__global__ __launch_bounds__(256) void k_istage1() {
    __shared__ float sS[MODES];
    int bo = blockIdx.x, x = threadIdx.x;
    for (int i = x; i < MODES; i += 256) sS[i] = g_spec2[(size_t)bo * MODES + i];
    __syncthreads();
    float g1r[RR];
    const float4* gp = (const float4*)(g_G1 + x * RR);
#pragma unroll
    for (int j = 0; j < RR / 4; j++) {
        float4 v = gp[j];
        g1r[4 * j] = v.x; g1r[4 * j + 1] = v.y; g1r[4 * j + 2] = v.z; g1r[4 * j + 3] = v.w;
    }
    float acc[M2];
#pragma unroll
    for (int s = 0; s < M2; s++) acc[s] = 0.f;
#pragma unroll 4
    for (int r = 0; r < RR; r++) {
        float g = g1r[r];
#pragma unroll
        for (int s = 0; s < M2; s++) acc[s] += g * sS[r * M2 + s];
    }
    float* tp = g_t2 + ((size_t)bo * NN + x) * M2;
#pragma unroll
    for (int s = 0; s < M2; s++) tp[s] = acc[s];
}

// ---------------- fused layer update (3xTF32, B pre-split in staging, in place) ----------
// OUT(64x256) = CW(64x64)*H(64x256) + T2(64x24)*G2T(24x256) + bias, [tanh]
__global__ __launch_bounds__(512, 2) void k_ilayer_mma(const float* __restrict__ conv_w,
                                                       const float* __restrict__ conv_b,
                                                       int l, int do_tanh) {
    extern __shared__ float smf[];
    float* sG  = smf;                            // [24][BP] fp32 (inline split)
    float* sA1 = sG + 24 * BP;                   // [64][AP] fp32 (inline split)
    float* sA2 = sA1 + 64 * AP;                  // [64][28] fp32 (inline split)
    unsigned* sHh = (unsigned*)(sA2 + 64 * 28);  // [16][BP] pre-split hi
    unsigned* sHl = sHh + 16 * BP;               // [16][BP] pre-split lo
    int x = blockIdx.x, b = blockIdx.y, tid = threadIdx.x;
    int wid = tid >> 5, lane = tid & 31, gid = lane >> 2, tig = lane & 3;
    int mt = wid & 3, nh = wid >> 2;
    int obase = mt * 16, ybase = nh * 64;

    const float* cw = conv_w + (size_t)l * CC * CC;
    for (int idx = tid; idx < 64 * AP; idx += 512) {
        int o = idx / AP, i = idx % AP;
        sA1[idx] = (i < 64) ? cw[o * 64 + i] : 0.f;
    }
    for (int idx = tid; idx < 64 * 28; idx += 512) {
        int o = idx / 28, s = idx % 28;
        sA2[idx] = (s < 20) ? g_t2[(((size_t)(b * 64 + o)) * NN + x) * M2 + s] : 0.f;
    }
    for (int idx = tid; idx < 24 * NN; idx += 512) {
        int s = idx >> 8, y = idx & 255;
        sG[s * BP + y] = (s < 20) ? g_G2[y * M2 + s] : 0.f;
    }
    __syncthreads();

    float bias0 = __ldg(&conv_b[l * 64 + obase + gid]);
    float bias1 = __ldg(&conv_b[l * 64 + obase + gid + 8]);
    float acc[8][4];
#pragma unroll
    for (int nt = 0; nt < 8; nt++) { acc[nt][0] = acc[nt][1] = bias0; acc[nt][2] = acc[nt][3] = bias1; }

    // DCT term: K = 24 (inline splits, small share of MMAs)
#pragma unroll
    for (int ks = 0; ks < 3; ks++) {
        int k0 = ks * 8;
        unsigned ah0, al0, ah1, al1, ah2, al2, ah3, al3;
        split_tf(sA2[(obase + gid) * 28 + k0 + tig], ah0, al0);
        split_tf(sA2[(obase + gid + 8) * 28 + k0 + tig], ah1, al1);
        split_tf(sA2[(obase + gid) * 28 + k0 + tig + 4], ah2, al2);
        split_tf(sA2[(obase + gid + 8) * 28 + k0 + tig + 4], ah3, al3);
#pragma unroll
        for (int nt = 0; nt < 8; nt++) {
            int n = ybase + nt * 8 + gid;
            unsigned bh0, bl0, bh1, bl1;
            split_tf(sG[(k0 + tig) * BP + n], bh0, bl0);
            split_tf(sG[(k0 + tig + 4) * BP + n], bh1, bl1);
            MMA3(acc[nt], ah0,ah1,ah2,ah3, al0,al1,al2,al3, bh0,bh1, bl0,bl1);
        }
    }

    // conv term: K = 64 in four chunks of 16, H staged PRE-SPLIT (kills 4x redundant splits)
    for (int hc = 0; hc < 4; hc++) {
        __syncthreads();
        for (int idx = tid; idx < 16 * 64; idx += 512) {
            int i = idx >> 6, q = idx & 63;
            float4 v = *(const float4*)&g_h[(((size_t)(b * 64 + hc * 16 + i)) * NN + x) * NN + q * 4];
            unsigned h0, l0, h1, l1, h2, l2, h3, l3;
            split_tf(v.x, h0, l0); split_tf(v.y, h1, l1);
            split_tf(v.z, h2, l2); split_tf(v.w, h3, l3);
            *(uint4*)&sHh[i * BP + q * 4] = make_uint4(h0, h1, h2, h3);
            *(uint4*)&sHl[i * BP + q * 4] = make_uint4(l0, l1, l2, l3);
        }
        __syncthreads();
#pragma unroll
        for (int ks = 0; ks < 2; ks++) {
            int k0 = ks * 8;
            int ca = hc * 16 + k0 + tig;
            unsigned ah0, al0, ah1, al1, ah2, al2, ah3, al3;
            split_tf(sA1[(obase + gid) * AP + ca], ah0, al0);
            split_tf(sA1[(obase + gid + 8) * AP + ca], ah1, al1);
            split_tf(sA1[(obase + gid) * AP + ca + 4], ah2, al2);
            split_tf(sA1[(obase + gid + 8) * AP + ca + 4], ah3, al3);
#pragma unroll
            for (int nt = 0; nt < 8; nt++) {
                int n = ybase + nt * 8 + gid;
                unsigned bh0 = sHh[(k0 + tig) * BP + n];
                unsigned bh1 = sHh[(k0 + tig + 4) * BP + n];
                unsigned bl0 = sHl[(k0 + tig) * BP + n];
                unsigned bl1 = sHl[(k0 + tig + 4) * BP + n];
                MMA3(acc[nt], ah0,ah1,ah2,ah3, al0,al1,al2,al3, bh0,bh1, bl0,bl1);
            }
        }
    }

    int r0 = obase + gid, r1 = r0 + 8;
    float* h0 = &g_h[(((size_t)(b * 64 + r0)) * NN + x) * NN];
    float* h1 = &g_h[(((size_t)(b * 64 + r1)) * NN + x) * NN];
#pragma unroll
    for (int nt = 0; nt < 8; nt++) {
        int y0 = ybase + nt * 8 + tig * 2;
        float d0 = acc[nt][0], d1 = acc[nt][1], d2 = acc[nt][2], d3 = acc[nt][3];
        if (do_tanh) { d0 = ftanh(d0); d1 = ftanh(d1); d2 = ftanh(d2); d3 = ftanh(d3); }
        *(float2*)&h0[y0] = make_float2(d0, d1);
        *(float2*)&h1[y0] = make_float2(d2, d3);
    }
}

// ---------------- fc1 (tanh) + fc2 fused (3xTF32, B pre-split in staging) ----------------
__global__ __launch_bounds__(512, 2) void k_fc12_mma(const float* __restrict__ w1,
                                                     const float* __restrict__ b1,
                                                     const float* __restrict__ w2,
                                                     const float* __restrict__ b2,
                                                     float* __restrict__ out) {
    extern __shared__ float smf[];
    float* sA = smf;                              // [128][AP] fp32
    unsigned* sHh = (unsigned*)(sA + 128 * AP);   // [32][BP]
    unsigned* sHl = sHh + 32 * BP;                // [32][BP]
    float* sred = (float*)(sHl + 32 * BP);        // [256]
    float* sb1  = sred + 256;                     // [128]
    float* sw2  = sb1 + 128;                      // [128]
    int x = blockIdx.x, b = blockIdx.y, tid = threadIdx.x;
    int wid = tid >> 5, lane = tid & 31, gid = lane >> 2, tig = lane & 3;
    int mt = wid & 7, nh = wid >> 3;
    int fbase = mt * 16, ybase = nh * 128;

    for (int idx = tid; idx < 128 * AP; idx += 512) {
        int f = idx / AP, c = idx % AP;
        sA[idx] = (c < 64) ? w1[c * FCN + f] : 0.f;
    }
    if (tid < 256) sred[tid] = 0.f;
    if (tid < 128) { sb1[tid] = b1[tid]; sw2[tid] = w2[tid]; }
    __syncthreads();

    float bias0 = sb1[fbase + gid], bias1 = sb1[fbase + gid + 8];
    float w20 = sw2[fbase + gid], w21 = sw2[fbase + gid + 8];
    float acc[16][4];
#pragma unroll
    for (int nt = 0; nt < 16; nt++) { acc[nt][0] = acc[nt][1] = bias0; acc[nt][2] = acc[nt][3] = bias1; }

    for (int hc = 0; hc < 2; hc++) {
        __syncthreads();
        for (int idx = tid; idx < 32 * 64; idx += 512) {
            int i = idx >> 6, q = idx & 63;
            float4 v = *(const float4*)&g_h[(((size_t)(b * 64 + hc * 32 + i)) * NN + x) * NN + q * 4];
            unsigned h0, l0, h1, l1, h2, l2, h3, l3;
            split_tf(v.x, h0, l0); split_tf(v.y, h1, l1);
            split_tf(v.z, h2, l2); split_tf(v.w, h3, l3);
            *(uint4*)&sHh[i * BP + q * 4] = make_uint4(h0, h1, h2, h3);
            *(uint4*)&sHl[i * BP + q * 4] = make_uint4(l0, l1, l2, l3);
        }
        __syncthreads();
#pragma unroll
        for (int ks = 0; ks < 4; ks++) {
            int k0 = ks * 8;
            int ca = hc * 32 + k0 + tig;
            unsigned ah0, al0, ah1, al1, ah2, al2, ah3, al3;
            split_tf(sA[(fbase + gid) * AP + ca], ah0, al0);
            split_tf(sA[(fbase + gid + 8) * AP + ca], ah1, al1);
            split_tf(sA[(fbase + gid) * AP + ca + 4], ah2, al2);
            split_tf(sA[(fbase + gid + 8) * AP + ca + 4], ah3, al3);
#pragma unroll
            for (int nt = 0; nt < 16; nt++) {
                int n = ybase + nt * 8 + gid;
                unsigned bh0 = sHh[(k0 + tig) * BP + n];
                unsigned bh1 = sHh[(k0 + tig + 4) * BP + n];
                unsigned bl0 = sHl[(k0 + tig) * BP + n];
                unsigned bl1 = sHl[(k0 + tig + 4) * BP + n];
                MMA3(acc[nt], ah0,ah1,ah2,ah3, al0,al1,al2,al3, bh0,bh1, bl0,bl1);
            }
        }
    }

#pragma unroll
    for (int nt = 0; nt < 16; nt++) {
        float p0 = ftanh(acc[nt][0]) * w20 + ftanh(acc[nt][2]) * w21;
        float p1 = ftanh(acc[nt][1]) * w20 + ftanh(acc[nt][3]) * w21;
#pragma unroll
        for (int m = 4; m < 32; m <<= 1) {
            p0 += __shfl_xor_sync(0xffffffffu, p0, m);
            p1 += __shfl_xor_sync(0xffffffffu, p1, m);
        }
        if (lane < 4) {
            int y0 = ybase + nt * 8 + lane * 2;
            atomicAdd(&sred[y0], p0);
            atomicAdd(&sred[y0 + 1], p1);
        }
    }
    __syncthreads();
    if (tid < 256)
        out[((size_t)b * NN + x) * NN + tid] = sred[tid] + __ldg(&b2[0]);
}

// ---------------- launch ----------------
extern "C" void kernel_launch(void* const* d_in, const int* in_sizes, int n_in,
                              void* d_out, int out_size) {
    const float* x      = (const float*)d_in[0];
    const float* fc0_w  = (const float*)d_in[1];
    const float* fc0_b  = (const float*)d_in[2];
    const float* sp_w1  = (const float*)d_in[3];
    const float* sp_w2  = (const float*)d_in[4];
    const float* conv_w = (const float*)d_in[5];
    const float* conv_b = (const float*)d_in[6];
    const float* fc1_w  = (const float*)d_in[7];
    const float* fc1_b  = (const float*)d_in[8];
    const float* fc2_w  = (const float*)d_in[9];
    const float* fc2_b  = (const float*)d_in[10];
    float* out = (float*)d_out;

    const int SM_S1P    = 2 * 256 * 24 * 4;                                      // 49152
    const int SM_ILAYER = (24 * BP + 64 * AP + 64 * 28 + 2 * 16 * BP) * 4;       // 83712
    const int SM_FC12   = (128 * AP + 2 * 32 * BP + 256 + 128 + 128) * 4;        // 104448

    cudaFuncSetAttribute(k_s1p, cudaFuncAttributeMaxDynamicSharedMemorySize, SM_S1P);
    cudaFuncSetAttribute(k_ilayer_mma, cudaFuncAttributeMaxDynamicSharedMemorySize, SM_ILAYER);
    cudaFuncSetAttribute(k_fc12_mma, cudaFuncAttributeMaxDynamicSharedMemorySize, SM_FC12);

    k_init<<<NN, 256>>>();
    k_wtrans<<<dim3(13, 128, LL * 2), dim3(32, 32)>>>(sp_w1, sp_w2);
    k_fc0<<<dim3(NN, BB), 256>>>(x, fc0_w, fc0_b);

    for (int l = 0; l < LL; l++) {
        k_s1p<<<(BB * CC * NN) / 128, 256, SM_S1P>>>();
        k_s2p<<<BB * CC, 256>>>();
        k_mix<<<MODES, 256>>>(l);
        k_istage1<<<BB * CC, 256>>>();
        k_ilayer_mma<<<dim3(NN, BB), 512, SM_ILAYER>>>(conv_w, conv_b, l, (l != LL - 1) ? 1 : 0);
    }

    k_fc12_mma<<<dim3(NN, BB), 512, SM_FC12>>>(fc1_w, fc1_b, fc2_w, fc2_b, out);
}